// round 15
// baseline (speedup 1.0000x reference)
#include <cuda_runtime.h>
#include <cuda_bf16.h>

#define NODES  100000
#define EDGES  1600000
#define F      128
#define NGRAPH 2048
#define SCAN_BLK 1024
#define SCAN_NBLK ((NODES + SCAN_BLK - 1) / SCAN_BLK)   // 98

typedef unsigned long long ull;

// Packed f32x2 helpers (sm_103a FFMA2 — PTX only, ptxas never auto-fuses)
#define FMA2(acc, a, b) \
    asm("fma.rn.f32x2 %0, %1, %2, %0;" : "+l"(acc) : "l"(a), "l"(b))
#define PACK2(out, lo, hi) \
    asm("mov.b64 %0, {%1, %2};" : "=l"(out) : "r"(__float_as_uint(lo)), "r"(__float_as_uint(hi)))
#define UNPACK2(lo, hi, in) \
    asm("mov.b64 {%0, %1}, %2;" : "=r"(lo), "=r"(hi) : "l"(in))

// GEMM dynamic smem layout: Xsd (64x128 ull = 64KB) + Ws (32x128 f32 = 16KB)
#define GEMM_SMEM (64 * 128 * 8 + 32 * 128 * 4)

// Scratch (device globals — allocations banned). 16B-aligned for float4.
__device__ __align__(16) float g_xw[NODES * F];    // X@W1
__device__ __align__(16) float g_z[NODES];         // z[n] = h[n]·(W2@Wlin)
__device__ __align__(16) float g_rdeg[NODES];      // rsqrt(deg incl self)
__device__ __align__(16) float g_wt[F];            // w~ = W2 @ Wlin
__device__ __align__(16) float g_pool1[NGRAPH];    // per-graph scalar sums
__device__ __align__(16) float g_cnt[NGRAPH];      // per-graph node counts
__device__ float g_c2;                             // dot(b2, Wlin)
__device__ int g_degi[NODES];                      // in-degree (no self loop)
__device__ int g_rowstart[NODES];                  // CSR row offsets
__device__ int g_fill[NODES];                      // CSR fill cursors (seeded = rowstart)
__device__ int g_csr[EDGES];                       // CSR src indices
__device__ int g_bsum[SCAN_NBLK];
__device__ int g_boff[SCAN_NBLK];
__device__ int g_sel;                              // which 128-vec is Wlin
__device__ int g_ei64;                             // edge_index int64?
__device__ int g_b64;                              // batch int64?

// ---------------------------------------------------------------------------
// Detect index dtypes + identify Wlin (the only nonzero 128-vec).
__global__ void k_inspect(const void* __restrict__ ei,
                          const void* __restrict__ batch,
                          const float* __restrict__ v0,
                          const float* __restrict__ v1,
                          const float* __restrict__ v2) {
    if (blockIdx.x != 0 || threadIdx.x != 0) return;
    const int* e32 = (const int*)ei;
    int allz = 1;
    for (int i = 1; i < 257; i += 2) if (e32[i] != 0) { allz = 0; break; }
    g_ei64 = allz;
    const int* b32 = (const int*)batch;
    allz = 1;
    for (int i = 99489; i < 100000; i += 2) if (b32[i] != 0) { allz = 0; break; }
    g_b64 = allz;
    float s0 = 0.f, s1 = 0.f, s2 = 0.f;
    for (int i = 0; i < 128; i++) {
        s0 += fabsf(v0[i]); s1 += fabsf(v1[i]); s2 += fabsf(v2[i]);
    }
    int s = 0; float m = s0;
    if (s1 > m) { m = s1; s = 1; }
    if (s2 > m) { s = 2; }
    g_sel = s;
}

__device__ __forceinline__ int loadIdx(const void* p, int i, int is64, int n) {
    int x = is64 ? (int)((const long long*)p)[i] : ((const int*)p)[i];
    return ((unsigned)x < (unsigned)n) ? x : 0;
}

// ---------------------------------------------------------------------------
// w~ = W2 @ Wlin  (128-vec) and c2 = dot(b2, Wlin). One block, 128 threads.
__global__ void k_wt(const float* __restrict__ W2,
                     const float* __restrict__ v0,
                     const float* __restrict__ v1,
                     const float* __restrict__ v2) {
    __shared__ float wl[F];
    __shared__ float red[F];
    int t = threadIdx.x;
    const float* wsel[3] = {v0, v1, v2};
    const float* Wlin = wsel[g_sel];
    const float* b2   = wsel[(g_sel + 2) % 3];
    wl[t] = Wlin[t];
    __syncthreads();
    float s = 0.f;
#pragma unroll 8
    for (int j = 0; j < F; j++) s = fmaf(W2[t * F + j], wl[j], s);
    g_wt[t] = s;
    red[t] = b2[t] * wl[t];
    __syncthreads();
    for (int off = 64; off > 0; off >>= 1) {
        if (t < off) red[t] += red[t + off];
        __syncthreads();
    }
    if (t == 0) g_c2 = red[0];
}

// ---------------------------------------------------------------------------
// Init: zero degi/pool1/cnt
__global__ void k_init() {
    int i = blockIdx.x * blockDim.x + threadIdx.x;
    if (i < NODES)  g_degi[i] = 0;
    if (i < NGRAPH) { g_pool1[i] = 0.f; g_cnt[i] = 0.f; }
}

// In-degree histogram + graph node counts (fused)
__global__ void k_deg(const void* __restrict__ ei,
                      const void* __restrict__ batch) {
    int e = blockIdx.x * blockDim.x + threadIdx.x;
    if (e < EDGES) atomicAdd(&g_degi[loadIdx(ei, EDGES + e, g_ei64, NODES)], 1);
    if (e < NODES) atomicAdd(&g_cnt[loadIdx(batch, e, g_b64, NGRAPH)], 1.f);
}

// ---------------------------------------------------------------------------
// Multi-block exclusive scan of g_degi -> g_rowstart.
__global__ __launch_bounds__(SCAN_BLK) void k_scan1() {
    __shared__ int sh[SCAN_BLK];
    int t = threadIdx.x;
    int i = blockIdx.x * SCAN_BLK + t;
    int v = (i < NODES) ? g_degi[i] : 0;
    sh[t] = v;
    __syncthreads();
    for (int off = 1; off < SCAN_BLK; off <<= 1) {
        int add = (t >= off) ? sh[t - off] : 0;
        __syncthreads();
        sh[t] += add;
        __syncthreads();
    }
    if (i < NODES) g_rowstart[i] = sh[t] - v;   // exclusive (pre-offset)
    if (t == SCAN_BLK - 1) g_bsum[blockIdx.x] = sh[t];
}

__global__ void k_scan2() {
    if (threadIdx.x != 0) return;
    int run = 0;
    for (int i = 0; i < SCAN_NBLK; i++) {
        g_boff[i] = run;
        run += g_bsum[i];
    }
}

// Apply block offsets; compute rdeg; seed fill cursors with rowstart.
__global__ __launch_bounds__(SCAN_BLK) void k_scan3() {
    int i = blockIdx.x * SCAN_BLK + threadIdx.x;
    if (i >= NODES) return;
    int rs = g_rowstart[i] + g_boff[blockIdx.x];
    g_rowstart[i] = rs;
    g_fill[i] = rs;
    g_rdeg[i] = rsqrtf((float)g_degi[i] + 1.0f);
}

// CSR fill: csr[cursor[dst]++] = src   (cursor pre-seeded with rowstart)
__global__ void k_fill(const void* __restrict__ ei) {
    int e = blockIdx.x * blockDim.x + threadIdx.x;
    if (e >= EDGES) return;
    int is64 = g_ei64;
    int s = loadIdx(ei, e, is64, NODES);
    int d = loadIdx(ei, EDGES + e, is64, NODES);
    int pos = atomicAdd(&g_fill[d], 1);
    g_csr[pos] = s;
}

// ---------------------------------------------------------------------------
// GEMM1: g_xw = X[N,128] @ W1[128,128], FFMA2 with zero in-loop packs and
// high W reuse. 64-row tile, 8 rows/thread; X stored as (x,x) pairs in smem
// (packed once at load). Dynamic smem: Xsd 64KB + Ws 16KB = 80KB.
__global__ __launch_bounds__(256) void k_gemm(const float* __restrict__ X,
                                              const float* __restrict__ W) {
    extern __shared__ char smem_raw[];
    ull   (*Xsd)[128] = (ull(*)[128])smem_raw;                 // 64KB
    float (*Ws)[128]  = (float(*)[128])(smem_raw + 64 * 1024); // 16KB

    int tx = threadIdx.x & 31;   // cols tx*4..tx*4+3
    int ty = threadIdx.x >> 5;   // rows ty*8..ty*8+7
    int rowBase = blockIdx.x * 64;

    // Load X tile, duplicating each float into a 64-bit (x,x) pair.
    for (int i = threadIdx.x; i < 64 * 32; i += 256) {
        int r = i >> 5;
        int c = (i & 31) * 4;
        float4 v = make_float4(0.f, 0.f, 0.f, 0.f);
        int gr = rowBase + r;
        if (gr < NODES) v = *(const float4*)&X[gr * F + c];
        ull p;
        PACK2(p, v.x, v.x); Xsd[r][c]     = p;
        PACK2(p, v.y, v.y); Xsd[r][c + 1] = p;
        PACK2(p, v.z, v.z); Xsd[r][c + 2] = p;
        PACK2(p, v.w, v.w); Xsd[r][c + 3] = p;
    }

    // acc2[r][0]=(c0,c1), acc2[r][1]=(c2,c3)
    ull acc2[8][2];
#pragma unroll
    for (int r = 0; r < 8; r++) { acc2[r][0] = 0ull; acc2[r][1] = 0ull; }

    for (int kk = 0; kk < 128; kk += 32) {
        __syncthreads();
        for (int i = threadIdx.x; i < 32 * 32; i += 256) {
            int r = i >> 5;
            int c = (i & 31) * 4;
            *(float4*)&Ws[r][c] = *(const float4*)&W[(kk + r) * F + c];
        }
        __syncthreads();
#pragma unroll
        for (int k = 0; k < 32; k += 2) {
            // one LDS.128 per k covers both column-pairs; reused across 8 rows
            ulonglong2 wA = *(const ulonglong2*)&Ws[k][tx * 4];
            ulonglong2 wB = *(const ulonglong2*)&Ws[k + 1][tx * 4];
#pragma unroll
            for (int r = 0; r < 8; r++) {
                // broadcast (x,x) pairs for k and k+1: one LDS.128
                ulonglong2 xr = *(const ulonglong2*)&Xsd[ty * 8 + r][kk + k];
                FMA2(acc2[r][0], xr.x, wA.x);
                FMA2(acc2[r][1], xr.x, wA.y);
                FMA2(acc2[r][0], xr.y, wB.x);
                FMA2(acc2[r][1], xr.y, wB.y);
            }
        }
    }

#pragma unroll
    for (int r = 0; r < 8; r++) {
        int gr = rowBase + ty * 8 + r;
        if (gr < NODES) {
            unsigned int o0, o1, o2, o3;
            UNPACK2(o0, o1, acc2[r][0]);
            UNPACK2(o2, o3, acc2[r][1]);
            *(float4*)&g_xw[gr * F + tx * 4] =
                make_float4(__uint_as_float(o0), __uint_as_float(o1),
                            __uint_as_float(o2), __uint_as_float(o3));
        }
    }
}

// ---------------------------------------------------------------------------
// Layer-1 aggregate+combine+relu fused directly into z, warp per node:
// h[d] = relu( rdeg[d]*sum_s rdeg[s]*xw[s] + xw[d]/deg[d] + b1 )  (in regs)
// z[d] = dot(h[d], w~)  — h never touches gmem.
__global__ __launch_bounds__(256) void k_agg_relu(const float* __restrict__ v0,
                                                  const float* __restrict__ v1,
                                                  const float* __restrict__ v2) {
    int node = (blockIdx.x * blockDim.x + threadIdx.x) >> 5;
    int lane = threadIdx.x & 31;
    if (node >= NODES) return;
    const float* bsel[3] = {v0, v1, v2};
    const float* b = bsel[(g_sel + 1) % 3];

    int start = g_rowstart[node];
    int n = g_degi[node];
    float4 acc = make_float4(0.f, 0.f, 0.f, 0.f);
    int j = 0;
    for (; j + 1 < n; j += 2) {
        int s0 = g_csr[start + j];
        int s1 = g_csr[start + j + 1];
        float w0 = g_rdeg[s0];
        float w1 = g_rdeg[s1];
        float4 a = *(const float4*)&g_xw[s0 * F + lane * 4];
        float4 c = *(const float4*)&g_xw[s1 * F + lane * 4];
        acc.x += a.x * w0 + c.x * w1;
        acc.y += a.y * w0 + c.y * w1;
        acc.z += a.z * w0 + c.z * w1;
        acc.w += a.w * w0 + c.w * w1;
    }
    if (j < n) {
        int s0 = g_csr[start + j];
        float w0 = g_rdeg[s0];
        float4 a = *(const float4*)&g_xw[s0 * F + lane * 4];
        acc.x += a.x * w0; acc.y += a.y * w0; acc.z += a.z * w0; acc.w += a.w * w0;
    }

    float rd = g_rdeg[node];
    float dinv = rd * rd;            // 1/deg
    float4 xw = *(const float4*)&g_xw[node * F + lane * 4];
    float4 bb = *(const float4*)&b[lane * 4];
    float4 h;
    h.x = fmaxf(acc.x * rd + xw.x * dinv + bb.x, 0.f);
    h.y = fmaxf(acc.y * rd + xw.y * dinv + bb.y, 0.f);
    h.z = fmaxf(acc.z * rd + xw.z * dinv + bb.z, 0.f);
    h.w = fmaxf(acc.w * rd + xw.w * dinv + bb.w, 0.f);

    // z[node] = dot(h[node], w~)
    float4 wt = *(const float4*)&g_wt[lane * 4];
    float zp = h.x * wt.x + h.y * wt.y + h.z * wt.z + h.w * wt.w;
#pragma unroll
    for (int o = 16; o > 0; o >>= 1) zp += __shfl_xor_sync(0xffffffffu, zp, o);
    if (lane == 0) g_z[node] = zp;
}

// ---------------------------------------------------------------------------
// Scalar layer-2: s[n] = rdeg[n]*sum_src rdeg[src]*z[src] + z[n]/deg[n];
// pool1[batch[n]] += s[n]. Thread per node.
__global__ __launch_bounds__(256) void k_agg2(const void* __restrict__ batch) {
    int node = blockIdx.x * blockDim.x + threadIdx.x;
    if (node >= NODES) return;
    int start = g_rowstart[node];
    int n = g_degi[node];
    float acc = 0.f;
#pragma unroll 4
    for (int j = 0; j < n; j++) {
        int s = g_csr[start + j];
        acc += g_z[s] * g_rdeg[s];
    }
    float rd = g_rdeg[node];
    float s = acc * rd + g_z[node] * rd * rd;
    atomicAdd(&g_pool1[loadIdx(batch, node, g_b64, NGRAPH)], s);
}

// ---------------------------------------------------------------------------
// Final: out[g] = pool1[g]/max(cnt,1) + c2 + blin
__global__ void k_final(const float* __restrict__ blin,
                        float* __restrict__ out) {
    int g = blockIdx.x * blockDim.x + threadIdx.x;
    if (g >= NGRAPH) return;
    out[g] = g_pool1[g] / fmaxf(g_cnt[g], 1.f) + g_c2 + blin[0];
}

// ---------------------------------------------------------------------------
extern "C" void kernel_launch(void* const* d_in, const int* in_sizes, int n_in,
                              void* d_out, int out_size) {
    const float* x     = nullptr;
    const void*  ei    = nullptr;
    const void*  batch = nullptr;
    const float* W1    = nullptr;
    const float* W2    = nullptr;
    const float* blin  = nullptr;
    const float* v128[3] = {nullptr, nullptr, nullptr};
    int n128 = 0;

    for (int i = 0; i < n_in; i++) {
        switch (in_sizes[i]) {
            case NODES * F:   x = (const float*)d_in[i];   break;
            case 2 * EDGES:   ei = d_in[i];                break;
            case NODES:       batch = d_in[i];             break;
            case F * F:       if (!W1) W1 = (const float*)d_in[i];
                              else     W2 = (const float*)d_in[i]; break;
            case F:           if (n128 < 3) v128[n128++] = (const float*)d_in[i]; break;
            case 1:           blin = (const float*)d_in[i]; break;
            default: break;
        }
    }
    float* out = (float*)d_out;

    // Opt in to 80KB dynamic smem for the GEMM (idempotent; not a stream op).
    cudaFuncSetAttribute(k_gemm, cudaFuncAttributeMaxDynamicSharedMemorySize,
                         GEMM_SMEM);

    const int edgeGrid = (EDGES + 255) / 256;
    const int nodeGrid = (NODES + 255) / 256;
    const int warpNodeGrid = (NODES * 32 + 255) / 256;  // warp per node
    const int gemmGrid = (NODES + 63) / 64;

    k_inspect<<<1, 32>>>(ei, batch, v128[0], v128[1], v128[2]);
    k_wt<<<1, 128>>>(W2, v128[0], v128[1], v128[2]);
    k_init<<<nodeGrid, 256>>>();
    k_deg<<<edgeGrid, 256>>>(ei, batch);
    k_scan1<<<SCAN_NBLK, SCAN_BLK>>>();
    k_scan2<<<1, 32>>>();
    k_scan3<<<SCAN_NBLK, SCAN_BLK>>>();
    k_fill<<<edgeGrid, 256>>>(ei);

    // Layer 1: GEMM + aggregate (h in regs, fused into z)
    k_gemm<<<gemmGrid, 256, GEMM_SMEM>>>(x, W1);
    k_agg_relu<<<warpNodeGrid, 256>>>(v128[0], v128[1], v128[2]);

    // Layer 2 collapsed to scalar aggregation + pooling
    k_agg2<<<nodeGrid, 256>>>(batch);

    k_final<<<(NGRAPH + 255) / 256, 256>>>(blin, out);
}

// round 17
// speedup vs baseline: 1.0462x; 1.0462x over previous
#include <cuda_runtime.h>
#include <cuda_bf16.h>
#include <cstdint>

#define NODES  100000
#define EDGES  1600000
#define F      128
#define NGRAPH 2048
#define SCAN_BLK 1024
#define SCAN_NBLK ((NODES + SCAN_BLK - 1) / SCAN_BLK)   // 98

#define K_PAD  136                       // bf16 elems per smem row (conflict-free ldmatrix)
#define GEMM_SMEM (4 * 128 * K_PAD * 2)  // Xhi,Xlo,Whi,Wlo = 139264 B

// ---------------------------------------------------------------------------
// Baseline-PTX tensor helpers (sm_80-era: work on compute_103 base target)
// ---------------------------------------------------------------------------
__device__ __forceinline__ uint32_t smem_u32(const void* p) {
    uint32_t a;
    asm("{ .reg .u64 t; cvta.to.shared.u64 t, %1; cvt.u32.u64 %0, t; }"
        : "=r"(a) : "l"(p));
    return a;
}
#define LDMATRIX_X4(r, addr) \
    asm volatile("ldmatrix.sync.aligned.m8n8.x4.shared.b16 {%0,%1,%2,%3}, [%4];" \
                 : "=r"((r)[0]), "=r"((r)[1]), "=r"((r)[2]), "=r"((r)[3]) : "r"(addr))
#define LDMATRIX_X2(r, addr) \
    asm volatile("ldmatrix.sync.aligned.m8n8.x2.shared.b16 {%0,%1}, [%2];" \
                 : "=r"((r)[0]), "=r"((r)[1]) : "r"(addr))
#define MMA_BF16(c, a, b) \
    asm volatile("mma.sync.aligned.m16n8k16.row.col.f32.bf16.bf16.f32 " \
                 "{%0,%1,%2,%3}, {%4,%5,%6,%7}, {%8,%9}, {%0,%1,%2,%3};" \
                 : "+f"((c)[0]), "+f"((c)[1]), "+f"((c)[2]), "+f"((c)[3]) \
                 : "r"((a)[0]), "r"((a)[1]), "r"((a)[2]), "r"((a)[3]), \
                   "r"((b)[0]), "r"((b)[1]))
// pack two fp32 -> bf16x2 (first arg -> low half)
#define CVT_PAIR(r, lo, hi) \
    asm("cvt.rn.satfinite.bf16x2.f32 %0, %1, %2;" : "=r"(r) : "f"(hi), "f"(lo))

// ---------------------------------------------------------------------------
// Scratch (device globals — allocations banned)
__device__ __align__(16) float g_xw[NODES * F];
__device__ __align__(16) float g_z[NODES];
__device__ __align__(16) float g_rdeg[NODES];
__device__ __align__(16) float g_wt[F];
__device__ __align__(16) float g_pool1[NGRAPH];
__device__ __align__(16) float g_cnt[NGRAPH];
__device__ float g_c2;
__device__ int g_degi[NODES];
__device__ int g_rowstart[NODES];
__device__ int g_fill[NODES];
__device__ int g_csr[EDGES];
__device__ int g_bsum[SCAN_NBLK];
__device__ int g_boff[SCAN_NBLK];
__device__ int g_sel;
__device__ int g_ei64;
__device__ int g_b64;
// W^T bf16 hi/lo images, [n][k] row-major (B col-major operand), 32KB each
__device__ __align__(16) __nv_bfloat16 g_wthi[F * F];
__device__ __align__(16) __nv_bfloat16 g_wtlo[F * F];

// ---------------------------------------------------------------------------
__global__ void k_inspect(const void* __restrict__ ei,
                          const void* __restrict__ batch,
                          const float* __restrict__ v0,
                          const float* __restrict__ v1,
                          const float* __restrict__ v2) {
    if (blockIdx.x != 0 || threadIdx.x != 0) return;
    const int* e32 = (const int*)ei;
    int allz = 1;
    for (int i = 1; i < 257; i += 2) if (e32[i] != 0) { allz = 0; break; }
    g_ei64 = allz;
    const int* b32 = (const int*)batch;
    allz = 1;
    for (int i = 99489; i < 100000; i += 2) if (b32[i] != 0) { allz = 0; break; }
    g_b64 = allz;
    float s0 = 0.f, s1 = 0.f, s2 = 0.f;
    for (int i = 0; i < 128; i++) {
        s0 += fabsf(v0[i]); s1 += fabsf(v1[i]); s2 += fabsf(v2[i]);
    }
    int s = 0; float m = s0;
    if (s1 > m) { m = s1; s = 1; }
    if (s2 > m) { s = 2; }
    g_sel = s;
}

__device__ __forceinline__ int loadIdx(const void* p, int i, int is64, int n) {
    int x = is64 ? (int)((const long long*)p)[i] : ((const int*)p)[i];
    return ((unsigned)x < (unsigned)n) ? x : 0;
}

// ---------------------------------------------------------------------------
// Build W^T hi/lo bf16 images: g_wthi[n*128+k] = bf16(W1[k*128+n]), lo = resid.
__global__ void k_wprep(const float* __restrict__ W1) {
    int idx = blockIdx.x * blockDim.x + threadIdx.x;
    if (idx >= F * F) return;
    int n = idx >> 7;
    int k = idx & 127;
    float w = W1[k * F + n];
    __nv_bfloat16 hi = __float2bfloat16(w);
    __nv_bfloat16 lo = __float2bfloat16(w - __bfloat162float(hi));
    g_wthi[n * F + k] = hi;
    g_wtlo[n * F + k] = lo;
}

// ---------------------------------------------------------------------------
__global__ void k_wt(const float* __restrict__ W2,
                     const float* __restrict__ v0,
                     const float* __restrict__ v1,
                     const float* __restrict__ v2) {
    __shared__ float wl[F];
    __shared__ float red[F];
    int t = threadIdx.x;
    const float* wsel[3] = {v0, v1, v2};
    const float* Wlin = wsel[g_sel];
    const float* b2   = wsel[(g_sel + 2) % 3];
    wl[t] = Wlin[t];
    __syncthreads();
    float s = 0.f;
#pragma unroll 8
    for (int j = 0; j < F; j++) s = fmaf(W2[t * F + j], wl[j], s);
    g_wt[t] = s;
    red[t] = b2[t] * wl[t];
    __syncthreads();
    for (int off = 64; off > 0; off >>= 1) {
        if (t < off) red[t] += red[t + off];
        __syncthreads();
    }
    if (t == 0) g_c2 = red[0];
}

__global__ void k_init() {
    int i = blockIdx.x * blockDim.x + threadIdx.x;
    if (i < NODES)  g_degi[i] = 0;
    if (i < NGRAPH) { g_pool1[i] = 0.f; g_cnt[i] = 0.f; }
}

__global__ void k_deg(const void* __restrict__ ei,
                      const void* __restrict__ batch) {
    int e = blockIdx.x * blockDim.x + threadIdx.x;
    if (e < EDGES) atomicAdd(&g_degi[loadIdx(ei, EDGES + e, g_ei64, NODES)], 1);
    if (e < NODES) atomicAdd(&g_cnt[loadIdx(batch, e, g_b64, NGRAPH)], 1.f);
}

__global__ __launch_bounds__(SCAN_BLK) void k_scan1() {
    __shared__ int sh[SCAN_BLK];
    int t = threadIdx.x;
    int i = blockIdx.x * SCAN_BLK + t;
    int v = (i < NODES) ? g_degi[i] : 0;
    sh[t] = v;
    __syncthreads();
    for (int off = 1; off < SCAN_BLK; off <<= 1) {
        int add = (t >= off) ? sh[t - off] : 0;
        __syncthreads();
        sh[t] += add;
        __syncthreads();
    }
    if (i < NODES) g_rowstart[i] = sh[t] - v;
    if (t == SCAN_BLK - 1) g_bsum[blockIdx.x] = sh[t];
}

__global__ void k_scan2() {
    if (threadIdx.x != 0) return;
    int run = 0;
    for (int i = 0; i < SCAN_NBLK; i++) { g_boff[i] = run; run += g_bsum[i]; }
}

__global__ __launch_bounds__(SCAN_BLK) void k_scan3() {
    int i = blockIdx.x * SCAN_BLK + threadIdx.x;
    if (i >= NODES) return;
    int rs = g_rowstart[i] + g_boff[blockIdx.x];
    g_rowstart[i] = rs;
    g_fill[i] = rs;
    g_rdeg[i] = rsqrtf((float)g_degi[i] + 1.0f);
}

__global__ void k_fill(const void* __restrict__ ei) {
    int e = blockIdx.x * blockDim.x + threadIdx.x;
    if (e >= EDGES) return;
    int is64 = g_ei64;
    int s = loadIdx(ei, e, is64, NODES);
    int d = loadIdx(ei, EDGES + e, is64, NODES);
    int pos = atomicAdd(&g_fill[d], 1);
    g_csr[pos] = s;
}

// ---------------------------------------------------------------------------
// Tensor-core GEMM: g_xw = X @ W1 via bf16 split (Xhi·Whi + Xhi·Wlo + Xlo·Whi).
// mma.sync.m16n8k16 bf16, fp32 accum. CTA: 256 thr, tile M=128,N=128,K=128.
// Warp w owns rows w*16..w*16+15; 16 n-tiles of 8; 8 k-steps of 16.
__global__ __launch_bounds__(256) void k_gemm(const float* __restrict__ X) {
    extern __shared__ __nv_bfloat16 sm[];
    __nv_bfloat16* Xhi = sm;
    __nv_bfloat16* Xlo = sm + 128 * K_PAD;
    __nv_bfloat16* Whi = sm + 2 * 128 * K_PAD;
    __nv_bfloat16* Wlo = sm + 3 * 128 * K_PAD;
    int tid = threadIdx.x;
    int rowBase = blockIdx.x * 128;

    // Stage W images (16B chunks; rows padded to K_PAD in smem).
    for (int i = tid; i < 128 * 16; i += 256) {       // 16 uint4 per 128-elem row
        int n = i >> 4;
        int k = (i & 15) * 8;
        *(uint4*)&Whi[n * K_PAD + k] = *(const uint4*)&g_wthi[n * F + k];
        *(uint4*)&Wlo[n * K_PAD + k] = *(const uint4*)&g_wtlo[n * F + k];
    }
    // Stage X, split into bf16 hi/lo.
    for (int i = tid; i < 128 * 32; i += 256) {       // 32 float4 per row
        int m = i >> 5;
        int k = (i & 31) * 4;
        int gr = rowBase + m;
        float4 v = (gr < NODES) ? *(const float4*)&X[gr * F + k]
                                : make_float4(0.f, 0.f, 0.f, 0.f);
        float hx = __bfloat162float(__float2bfloat16(v.x));
        float hy = __bfloat162float(__float2bfloat16(v.y));
        float hz = __bfloat162float(__float2bfloat16(v.z));
        float hw = __bfloat162float(__float2bfloat16(v.w));
        uint32_t p0, p1;
        CVT_PAIR(p0, hx, hy);
        CVT_PAIR(p1, hz, hw);
        *(uint2*)&Xhi[m * K_PAD + k] = make_uint2(p0, p1);
        CVT_PAIR(p0, v.x - hx, v.y - hy);
        CVT_PAIR(p1, v.z - hz, v.w - hw);
        *(uint2*)&Xlo[m * K_PAD + k] = make_uint2(p0, p1);
    }
    __syncthreads();

    int warp = tid >> 5;
    int lane = tid & 31;
    int m0 = warp * 16;

    float c[16][4];
#pragma unroll
    for (int nt = 0; nt < 16; nt++)
#pragma unroll
        for (int q = 0; q < 4; q++) c[nt][q] = 0.f;

    // ldmatrix address components
    int arow = m0 + (lane & 7) + ((lane >> 3) & 1) * 8;  // A tile rows
    int aksel = ((lane >> 4) & 1) * 8;                   // A tile k-half
    int bl = lane & 15;
    int bn = bl & 7;                                      // B tile row (n)
    int bk = (bl >> 3) * 8;                               // B tile k-half

    for (int ks = 0; ks < 8; ks++) {
        int k0 = ks * 16;
        uint32_t ahi[4], alo[4];
        LDMATRIX_X4(ahi, smem_u32(&Xhi[arow * K_PAD + k0 + aksel]));
        LDMATRIX_X4(alo, smem_u32(&Xlo[arow * K_PAD + k0 + aksel]));
#pragma unroll
        for (int nt = 0; nt < 16; nt++) {
            uint32_t bhi[2], blo[2];
            LDMATRIX_X2(bhi, smem_u32(&Whi[(nt * 8 + bn) * K_PAD + k0 + bk]));
            LDMATRIX_X2(blo, smem_u32(&Wlo[(nt * 8 + bn) * K_PAD + k0 + bk]));
            MMA_BF16(c[nt], ahi, bhi);
            MMA_BF16(c[nt], ahi, blo);
            MMA_BF16(c[nt], alo, bhi);
        }
    }

    // Epilogue: c fragment -> g_xw (float2 per half-row per n-tile)
    int g = lane >> 2;
    int tg = lane & 3;
    int r0 = rowBase + m0 + g;
    int r1 = r0 + 8;
#pragma unroll
    for (int nt = 0; nt < 16; nt++) {
        int col = nt * 8 + tg * 2;
        if (r0 < NODES) *(float2*)&g_xw[r0 * F + col] = make_float2(c[nt][0], c[nt][1]);
        if (r1 < NODES) *(float2*)&g_xw[r1 * F + col] = make_float2(c[nt][2], c[nt][3]);
    }
}

// ---------------------------------------------------------------------------
// Layer-1 aggregate+combine+relu fused into z, warp per node.
__global__ __launch_bounds__(256) void k_agg_relu(const float* __restrict__ v0,
                                                  const float* __restrict__ v1,
                                                  const float* __restrict__ v2) {
    int node = (blockIdx.x * blockDim.x + threadIdx.x) >> 5;
    int lane = threadIdx.x & 31;
    if (node >= NODES) return;
    const float* bsel[3] = {v0, v1, v2};
    const float* b = bsel[(g_sel + 1) % 3];

    int start = g_rowstart[node];
    int n = g_degi[node];
    float4 acc = make_float4(0.f, 0.f, 0.f, 0.f);
    int j = 0;
    for (; j + 1 < n; j += 2) {
        int s0 = g_csr[start + j];
        int s1 = g_csr[start + j + 1];
        float w0 = g_rdeg[s0];
        float w1 = g_rdeg[s1];
        float4 a = *(const float4*)&g_xw[s0 * F + lane * 4];
        float4 c = *(const float4*)&g_xw[s1 * F + lane * 4];
        acc.x += a.x * w0 + c.x * w1;
        acc.y += a.y * w0 + c.y * w1;
        acc.z += a.z * w0 + c.z * w1;
        acc.w += a.w * w0 + c.w * w1;
    }
    if (j < n) {
        int s0 = g_csr[start + j];
        float w0 = g_rdeg[s0];
        float4 a = *(const float4*)&g_xw[s0 * F + lane * 4];
        acc.x += a.x * w0; acc.y += a.y * w0; acc.z += a.z * w0; acc.w += a.w * w0;
    }

    float rd = g_rdeg[node];
    float dinv = rd * rd;
    float4 xw = *(const float4*)&g_xw[node * F + lane * 4];
    float4 bb = *(const float4*)&b[lane * 4];
    float4 h;
    h.x = fmaxf(acc.x * rd + xw.x * dinv + bb.x, 0.f);
    h.y = fmaxf(acc.y * rd + xw.y * dinv + bb.y, 0.f);
    h.z = fmaxf(acc.z * rd + xw.z * dinv + bb.z, 0.f);
    h.w = fmaxf(acc.w * rd + xw.w * dinv + bb.w, 0.f);

    float4 wt = *(const float4*)&g_wt[lane * 4];
    float zp = h.x * wt.x + h.y * wt.y + h.z * wt.z + h.w * wt.w;
#pragma unroll
    for (int o = 16; o > 0; o >>= 1) zp += __shfl_xor_sync(0xffffffffu, zp, o);
    if (lane == 0) g_z[node] = zp;
}

// ---------------------------------------------------------------------------
__global__ __launch_bounds__(256) void k_agg2(const void* __restrict__ batch) {
    int node = blockIdx.x * blockDim.x + threadIdx.x;
    if (node >= NODES) return;
    int start = g_rowstart[node];
    int n = g_degi[node];
    float acc = 0.f;
#pragma unroll 4
    for (int j = 0; j < n; j++) {
        int s = g_csr[start + j];
        acc += g_z[s] * g_rdeg[s];
    }
    float rd = g_rdeg[node];
    float s = acc * rd + g_z[node] * rd * rd;
    atomicAdd(&g_pool1[loadIdx(batch, node, g_b64, NGRAPH)], s);
}

__global__ void k_final(const float* __restrict__ blin,
                        float* __restrict__ out) {
    int g = blockIdx.x * blockDim.x + threadIdx.x;
    if (g >= NGRAPH) return;
    out[g] = g_pool1[g] / fmaxf(g_cnt[g], 1.f) + g_c2 + blin[0];
}

// ---------------------------------------------------------------------------
extern "C" void kernel_launch(void* const* d_in, const int* in_sizes, int n_in,
                              void* d_out, int out_size) {
    const float* x     = nullptr;
    const void*  ei    = nullptr;
    const void*  batch = nullptr;
    const float* W1    = nullptr;
    const float* W2    = nullptr;
    const float* blin  = nullptr;
    const float* v128[3] = {nullptr, nullptr, nullptr};
    int n128 = 0;

    for (int i = 0; i < n_in; i++) {
        switch (in_sizes[i]) {
            case NODES * F:   x = (const float*)d_in[i];   break;
            case 2 * EDGES:   ei = d_in[i];                break;
            case NODES:       batch = d_in[i];             break;
            case F * F:       if (!W1) W1 = (const float*)d_in[i];
                              else     W2 = (const float*)d_in[i]; break;
            case F:           if (n128 < 3) v128[n128++] = (const float*)d_in[i]; break;
            case 1:           blin = (const float*)d_in[i]; break;
            default: break;
        }
    }
    float* out = (float*)d_out;

    cudaFuncSetAttribute(k_gemm, cudaFuncAttributeMaxDynamicSharedMemorySize,
                         GEMM_SMEM);

    const int edgeGrid = (EDGES + 255) / 256;
    const int nodeGrid = (NODES + 255) / 256;
    const int warpNodeGrid = (NODES * 32 + 255) / 256;
    const int gemmGrid = (NODES + 127) / 128;   // 782

    k_inspect<<<1, 32>>>(ei, batch, v128[0], v128[1], v128[2]);
    k_wprep<<<(F * F + 255) / 256, 256>>>(W1);
    k_wt<<<1, 128>>>(W2, v128[0], v128[1], v128[2]);
    k_init<<<nodeGrid, 256>>>();
    k_deg<<<edgeGrid, 256>>>(ei, batch);
    k_scan1<<<SCAN_NBLK, SCAN_BLK>>>();
    k_scan2<<<1, 32>>>();
    k_scan3<<<SCAN_NBLK, SCAN_BLK>>>();
    k_fill<<<edgeGrid, 256>>>(ei);

    k_gemm<<<gemmGrid, 256, GEMM_SMEM>>>(x);
    k_agg_relu<<<warpNodeGrid, 256>>>(v128[0], v128[1], v128[2]);
    k_agg2<<<nodeGrid, 256>>>(batch);

    k_final<<<(NGRAPH + 255) / 256, 256>>>(blin, out);
}